// round 11
// baseline (speedup 1.0000x reference)
#include <cuda_runtime.h>
#include <cstdint>

#define B_TOTAL   262144
#define NE        128
#define RR        256
#define RANK      16
#define THREADS   512
#define NWARPS    16
#define ROWS_PER_TILE 64                       // 16 warps x 4 matrices
#define NTILES    (B_TOTAL / ROWS_PER_TILE)    // 4096
#define OSTRIDE   128                          // occ row stride (broadcast reads -> no pad)
#define W_FLOATS  (NE * RR)                    // 32768
#define OBUF_FLOATS (ROWS_PER_TILE * OSTRIDE)  // 8192
#define STAGE_PER_GROUP 272                    // 16 rows x stride 17 (conflict-free transpose)
#define STAGE_FLOATS (NWARPS * 2 * STAGE_PER_GROUP)  // 8704
#define SMEM_FLOATS (W_FLOATS + 2 * OBUF_FLOATS + STAGE_FLOATS)  // 57856 floats = 231424 B

typedef unsigned long long u64;

__device__ __forceinline__ u64 pack_f32x2(float lo, float hi) {
    u64 r;
    asm("mov.b64 %0, {%1, %2};" : "=l"(r) : "f"(lo), "f"(hi));
    return r;
}
__device__ __forceinline__ void unpack_f32x2(u64 v, float& lo, float& hi) {
    asm("mov.b64 {%0, %1}, %2;" : "=f"(lo), "=f"(hi) : "l"(v));
}
// d = a*b + c, two packed fp32 lanes, .rn per lane (bit-identical to scalar fmaf)
__device__ __forceinline__ u64 fma_f32x2(u64 a, u64 b, u64 c) {
    u64 d;
    asm("fma.rn.f32x2 %0, %1, %2, %3;" : "=l"(d) : "l"(a), "l"(b), "l"(c));
    return d;
}

__device__ __forceinline__ void cp_async16(void* dst_smem, const void* src) {
    unsigned d = (unsigned)__cvta_generic_to_shared(dst_smem);
    asm volatile("cp.async.ca.shared.global [%0], [%1], 16;" :: "r"(d), "l"(src) : "memory");
}
__device__ __forceinline__ void cp_commit() {
    asm volatile("cp.async.commit_group;" ::: "memory");
}
__device__ __forceinline__ void cp_wait1() {
    asm volatile("cp.async.wait_group 1;" ::: "memory");
}

// No-swap LU with partial pivoting. Each of 16 lanes holds one row in a[16].
// Pivot parity tracked via inversion counting (popc) instead of physical swaps.
__device__ __forceinline__ void lu_slogdet(float a[RANK], int li, int g, unsigned hmask,
                                           float& sign, float& logabs)
{
    sign = 1.0f;
    logabs = 0.0f;
    unsigned used = 0;                         // group-local lane bitmask (uniform)
    #pragma unroll
    for (int k = 0; k < RANK; k++) {
        bool avail = !((used >> li) & 1u);
        float v = avail ? fabsf(a[k]) : -1.0f;
        float mv = v;
        #pragma unroll
        for (int off = 8; off; off >>= 1)
            mv = fmaxf(mv, __shfl_xor_sync(hmask, mv, off, 16));
        unsigned bal = __ballot_sync(hmask, v == mv);
        int p = __ffs((int)(g ? (bal >> 16) : (bal & 0xFFFFu))) - 1;   // 0..15, uniform

        float piv = __shfl_sync(hmask, a[k], p, 16);

        // parity: inversions added by choosing lane p now = #unused lanes below p
        unsigned ub = (~used) & ((1u << p) - 1u) & 0xFFFFu;
        if (__popc(ub) & 1) sign = -sign;
        if (piv < 0.0f)     sign = -sign;
        logabs += __logf(fabsf(piv));
        used |= 1u << p;

        float f = (avail && li != p) ? __fdividef(a[k], piv) : 0.0f;
        #pragma unroll
        for (int j = 0; j < RANK; j++) {
            if (j >= k + 1) {
                float prj = __shfl_sync(hmask, a[j], p, 16);
                a[j] = fmaf(-f, prj, a[j]);
            }
        }
    }
}

__global__ void __launch_bounds__(THREADS, 1)
jastrow_slogdet_kernel(const float* __restrict__ occ,
                       const float* __restrict__ Wg,
                       const float* __restrict__ bvec,
                       float* __restrict__ out)
{
    extern __shared__ float smem[];
    float* Wsh   = smem;                                  // [128][256]
    float* Osh   = smem + W_FLOATS;                       // 2 x [64][128]
    float* Stage = smem + W_FLOATS + 2 * OBUF_FLOATS;     // 16 warps x 2 groups x (16x17)

    const int tid  = threadIdx.x;
    const int w    = tid >> 5;
    const int lane = tid & 31;
    const int g    = lane >> 4;
    const int li   = lane & 15;
    const unsigned hmask = (lane < 16) ? 0x0000FFFFu : 0xFFFF0000u;

    // ---- Load W into SMEM once (stays resident) ----
    {
        const float4* W4  = (const float4*)Wg;
        float4*       Ws4 = (float4*)Wsh;
        #pragma unroll
        for (int i = 0; i < W_FLOATS / 4 / THREADS; i++)      // 16 iters
            Ws4[tid + i * THREADS] = W4[tid + i * THREADS];
    }

    // ---- b values for this lane's 16 output columns (cols c = i*64 + li*4 + q) ----
    float4 bb[4];
    #pragma unroll
    for (int i = 0; i < 4; i++)
        bb[i] = ((const float4*)bvec)[i * 16 + li];

    float* st = Stage + (w * 2 + g) * STAGE_PER_GROUP;

    // ---- Prefetch first occ tile ----
    int t0 = (int)blockIdx.x;
    int buf = 0;
    if (t0 < NTILES) {
        const float4* src = (const float4*)(occ + (size_t)t0 * ROWS_PER_TILE * NE);
        #pragma unroll
        for (int i = 0; i < 4; i++) {                // 2048 float4 / 512 threads
            int idx = tid + i * THREADS;
            int r = idx >> 5, c = idx & 31;          // 32 float4 per row
            cp_async16(Osh + r * OSTRIDE + c * 4, src + idx);
        }
    }
    cp_commit();

    for (int t = t0; t < NTILES; t += (int)gridDim.x) {
        int tn   = t + (int)gridDim.x;
        int nbuf = buf ^ 1;
        if (tn < NTILES) {
            const float4* src = (const float4*)(occ + (size_t)tn * ROWS_PER_TILE * NE);
            #pragma unroll
            for (int i = 0; i < 4; i++) {
                int idx = tid + i * THREADS;
                int r = idx >> 5, c = idx & 31;
                cp_async16(Osh + nbuf * OBUF_FLOATS + r * OSTRIDE + c * 4, src + idx);
            }
        }
        cp_commit();
        cp_wait1();                // current buf landed
        __syncthreads();

        // ======== GEMM: each 16-lane group computes TWO batch rows ========
        // group g of warp w owns matrices m0 = w*4 + g*2, m1 = m0 + 1
        // Packed f32x2 accumulators: acc2[s][i*2+0] = cols (i*64+li*4+0, +1),
        //                            acc2[s][i*2+1] = cols (i*64+li*4+2, +3)
        const float* orow0 = Osh + buf * OBUF_FLOATS + (w * 4 + g * 2 + 0) * OSTRIDE;
        const float* orow1 = Osh + buf * OBUF_FLOATS + (w * 4 + g * 2 + 1) * OSTRIDE;

        u64 acc2[2][8];
        #pragma unroll
        for (int i = 0; i < 4; i++) {
            u64 p01 = pack_f32x2(bb[i].x, bb[i].y);
            u64 p23 = pack_f32x2(bb[i].z, bb[i].w);
            acc2[0][i*2+0] = p01; acc2[0][i*2+1] = p23;
            acc2[1][i*2+0] = p01; acc2[1][i*2+1] = p23;
        }

        #pragma unroll 2
        for (int k4 = 0; k4 < NE / 4; k4++) {
            float4 o0 = ((const float4*)orow0)[k4];   // broadcast within group
            float4 o1 = ((const float4*)orow1)[k4];
            float oa[4] = {o0.x, o0.y, o0.z, o0.w};
            float ob[4] = {o1.x, o1.y, o1.z, o1.w};
            #pragma unroll
            for (int kk = 0; kk < 4; kk++) {
                const ulonglong2* wrow2 =
                    (const ulonglong2*)(Wsh + (k4 * 4 + kk) * RR);
                u64 va = pack_f32x2(oa[kk], oa[kk]);
                u64 vb = pack_f32x2(ob[kk], ob[kk]);
                #pragma unroll
                for (int i = 0; i < 4; i++) {
                    ulonglong2 wv = wrow2[i * 16 + li];   // 16B-aligned LDS.128
                    acc2[0][i*2+0] = fma_f32x2(va, wv.x, acc2[0][i*2+0]);
                    acc2[0][i*2+1] = fma_f32x2(va, wv.y, acc2[0][i*2+1]);
                    acc2[1][i*2+0] = fma_f32x2(vb, wv.x, acc2[1][i*2+0]);
                    acc2[1][i*2+1] = fma_f32x2(vb, wv.y, acc2[1][i*2+1]);
                }
            }
        }

        // ======== per matrix: transpose via stride-17 smem, then LU ========
        #pragma unroll
        for (int s = 0; s < 2; s++) {
            // cols c0 = i*64 + li*4 (+0..3) -> element (c>>4, c&15).
            // SCALAR stores only: stride-17 rows make float4 addresses
            // misaligned for odd rows (68B offsets) -> STS.128 trap. 4B stores
            // are always legal and keep the conflict-free stride.
            #pragma unroll
            for (int i = 0; i < 4; i++) {
                int c0 = i * 64 + li * 4;
                float v0, v1, v2, v3;
                unpack_f32x2(acc2[s][i*2+0], v0, v1);
                unpack_f32x2(acc2[s][i*2+1], v2, v3);
                float* p = st + (c0 >> 4) * 17 + (c0 & 15);
                p[0] = v0; p[1] = v1; p[2] = v2; p[3] = v3;
            }
            __syncwarp();
            float a[RANK];
            #pragma unroll
            for (int j = 0; j < RANK; j++)
                a[j] = st[li * 17 + j] + ((j == li) ? 1.0f : 0.0f);
            __syncwarp();          // done reading before next s overwrites

            float sign, logabs;
            lu_slogdet(a, li, g, hmask, sign, logabs);

            if (li == 0) {
                int gr = t * ROWS_PER_TILE + w * 4 + g * 2 + s;
                out[gr]           = sign;
                out[B_TOTAL + gr] = logabs;
            }
        }

        __syncthreads();           // everyone done with buf before it is re-prefetched
        buf ^= 1;
    }
}

extern "C" void kernel_launch(void* const* d_in, const int* in_sizes, int n_in,
                              void* d_out, int out_size) {
    const float* occ = (const float*)d_in[0];
    const float* Wg  = (const float*)d_in[1];
    const float* bv  = (const float*)d_in[2];
    float* out = (float*)d_out;

    int dev = 0;
    cudaGetDevice(&dev);
    int sms = 148;
    cudaDeviceGetAttribute(&sms, cudaDevAttrMultiProcessorCount, dev);
    int grid = sms;                 // 231 KB smem => exactly 1 CTA/SM resident

    size_t smem_bytes = SMEM_FLOATS * sizeof(float);   // 231424 B
    cudaFuncSetAttribute(jastrow_slogdet_kernel,
                         cudaFuncAttributeMaxDynamicSharedMemorySize,
                         (int)smem_bytes);

    jastrow_slogdet_kernel<<<grid, THREADS, smem_bytes>>>(occ, Wg, bv, out);
}